// round 6
// baseline (speedup 1.0000x reference)
#include <cuda_runtime.h>

#define EPS 0.001f

// Table: 64 mask entries, each 4 x float4 at stride 5 float4s (80B).
// Quad-start bank = (20*m)%32 covers all 8 quad positions over m mod 8
// -> near-conflict-free LDS.128 with random masks.
//  e0 = {S00,S01,S10,S11}   pre-mask Jacobian of s3
//  e1 = {sb0,sb1,E0,E1}     s3 bias, dlo_dq
//  e2 = {lb,G00,G01,G10}    lo bias, g-matrix
//  e3 = {G11,gb0,gb1,pad}

__device__ __forceinline__ void compute_row(
    float q0, float q1, float qd0, float qd1, float qdd0, float qdd1,
    const float* __restrict__ w1r, const float* __restrict__ b1r,
    const float4* __restrict__ tab4, float& t0, float& t1)
{
    // ReLU mask from the 6 hidden pre-activations (only W1/b1 needed)
    int mask = 0;
#pragma unroll
    for (int j = 0; j < 6; j++) {
        float z = fmaf(w1r[2 * j], q0, fmaf(w1r[2 * j + 1], q1, b1r[j]));
        mask |= (int)(z > 0.0f) << j;
    }

    const float4* e = tab4 + mask * 5;
    const float4 e0 = e[0], e1 = e[1], e2 = e[2], e3 = e[3];

    const float S00 = e0.x, S01 = e0.y, S10 = e0.z, S11 = e0.w;
    const float s30 = fmaf(S00, q0, fmaf(S01, q1, e1.x));
    const float s31 = fmaf(S10, q0, fmaf(S11, q1, e1.y));
    const float E0 = e1.z, E1 = e1.w;
    const float c = fmaf(E0, q0, fmaf(E1, q1, e2.x));            // lo
    const float g0 = fmaf(e2.y, q0, fmaf(e2.z, q1, e3.y));
    const float g1 = fmaf(e2.w, q0, fmaf(e3.x, q1, e3.z));

    const float a = fmaxf(s30, 0.0f);
    const float b = fmaxf(s31, 0.0f);
    const float m0 = (s30 > 0.0f) ? 1.0f : 0.0f;
    const float m1 = (s31 > 0.0f) ? 1.0f : 0.0f;

    const float d00 = S00 * m0, d01 = S01 * m0;
    const float d10 = S10 * m1, d11 = S11 * m1;

    // time derivatives
    const float da = fmaf(d00, qd0, d01 * qd1);
    const float db = fmaf(d10, qd0, d11 * qd1);
    const float dc = fmaf(E0,  qd0, E1  * qd1);

    // H q_ddot = L^T (L q_ddot) + eps q_ddot,  L = [[a,0],[c,b]]
    const float Lq0 = a * qdd0;
    const float Lq1 = fmaf(c, qdd0, b * qdd1);
    const float Hq0 = fmaf(a, Lq0, fmaf(c, Lq1, EPS * qdd0));
    const float Hq1 = fmaf(b, Lq1, EPS * qdd1);

    // dH_dt terms
    const float dh01 = fmaf(a, dc, c * da);
    const float dHq0 = fmaf(2.0f * a * da, qd0, dh01 * qd1);
    const float dHq1 = fmaf(dh01, qd0, 2.0f * fmaf(c, dc, b * db) * qd1);

    // quad_i = 2 (B_i^T qd) . (L^T qd)
    const float Ltq0 = fmaf(a, qd0, c * qd1);
    const float Ltq1 = b * qd1;
    const float quad0 = 2.0f * fmaf(fmaf(d00, qd0, E0 * qd1), Ltq0, d10 * qd1 * Ltq1);
    const float quad1 = 2.0f * fmaf(fmaf(d01, qd0, E1 * qd1), Ltq0, d11 * qd1 * Ltq1);

    t0 = Hq0 + dHq0 + quad0 + g0;
    t1 = Hq1 + dHq1 + quad1 + g1;
}

__global__ void __launch_bounds__(128, 8)
lnn_tau_kernel(const float* __restrict__ x,
               const float* __restrict__ W1, const float* __restrict__ b1,
               const float* __restrict__ W2, const float* __restrict__ b2,
               const float* __restrict__ W3, const float* __restrict__ b3,
               const float* __restrict__ W4, const float* __restrict__ b4,
               float* __restrict__ out, int n)
{
    __shared__ float4 tab4[64 * 5];

    // Build the 64-entry piecewise-linear table.
    if (threadIdx.x < 64) {
        const int m = threadIdx.x;
        float S00 = 0.f, S01 = 0.f, S10 = 0.f, S11 = 0.f;
        float sb0 = b3[0], sb1 = b3[1];
        float E0 = 0.f, E1 = 0.f, lb = b4[0];
        float G00 = 0.f, G01 = 0.f, G10 = 0.f, G11 = 0.f;
        float gb0 = b2[0], gb1 = b2[1];
#pragma unroll
        for (int j = 0; j < 6; j++) {
            if ((m >> j) & 1) {
                const float a0 = W1[2 * j], a1 = W1[2 * j + 1], bb = b1[j];
                const float w30 = W3[j], w31 = W3[6 + j];
                const float w20 = W2[j], w21 = W2[6 + j];
                const float w4j = W4[j];
                S00 = fmaf(w30, a0, S00); S01 = fmaf(w30, a1, S01); sb0 = fmaf(w30, bb, sb0);
                S10 = fmaf(w31, a0, S10); S11 = fmaf(w31, a1, S11); sb1 = fmaf(w31, bb, sb1);
                E0  = fmaf(w4j, a0, E0);  E1  = fmaf(w4j, a1, E1);  lb  = fmaf(w4j, bb, lb);
                G00 = fmaf(w20, a0, G00); G01 = fmaf(w20, a1, G01); gb0 = fmaf(w20, bb, gb0);
                G10 = fmaf(w21, a0, G10); G11 = fmaf(w21, a1, G11); gb1 = fmaf(w21, bb, gb1);
            }
        }
        float4* e = tab4 + m * 5;
        e[0] = make_float4(S00, S01, S10, S11);
        e[1] = make_float4(sb0, sb1, E0, E1);
        e[2] = make_float4(lb, G00, G01, G10);
        e[3] = make_float4(G11, gb0, gb1, 0.0f);
    }

    // Only W1/b1 needed per-thread (mask planes): 18 registers.
    float w1r[12], b1r[6];
#pragma unroll
    for (int j = 0; j < 6; j++) {
        w1r[2 * j]     = __ldg(W1 + 2 * j);
        w1r[2 * j + 1] = __ldg(W1 + 2 * j + 1);
        b1r[j]         = __ldg(b1 + j);
    }
    __syncthreads();

    const int np = n >> 1;  // pairs of rows
    const int tid = blockIdx.x * blockDim.x + threadIdx.x;

    if (tid < np) {
        const float4* xp = reinterpret_cast<const float4*>(x + (size_t)tid * 12);
        const float4 u0 = xp[0], u1 = xp[1], u2 = xp[2];

        float o0, o1, o2, o3;
        compute_row(u0.x, u0.y, u0.z, u0.w, u1.x, u1.y, w1r, b1r, tab4, o0, o1);
        compute_row(u1.z, u1.w, u2.x, u2.y, u2.z, u2.w, w1r, b1r, tab4, o2, o3);

        reinterpret_cast<float4*>(out)[tid] = make_float4(o0, o1, o2, o3);
    }

    // Tail (n odd) — n is even here; kept for safety.
    if ((n & 1) && blockIdx.x == 0 && threadIdx.x == 0) {
        const int row = n - 1;
        float t0, t1;
        compute_row(x[(size_t)row * 6 + 0], x[(size_t)row * 6 + 1],
                    x[(size_t)row * 6 + 2], x[(size_t)row * 6 + 3],
                    x[(size_t)row * 6 + 4], x[(size_t)row * 6 + 5],
                    w1r, b1r, tab4, t0, t1);
        out[(size_t)row * 2 + 0] = t0;
        out[(size_t)row * 2 + 1] = t1;
    }
}

extern "C" void kernel_launch(void* const* d_in, const int* in_sizes, int n_in,
                              void* d_out, int out_size)
{
    const float* x  = (const float*)d_in[0];
    const float* W1 = (const float*)d_in[1];
    const float* b1 = (const float*)d_in[2];
    const float* W2 = (const float*)d_in[3];
    const float* b2 = (const float*)d_in[4];
    const float* W3 = (const float*)d_in[5];
    const float* b3 = (const float*)d_in[6];
    const float* W4 = (const float*)d_in[7];
    const float* b4 = (const float*)d_in[8];
    float* out = (float*)d_out;

    const int n = in_sizes[0] / 6;   // rows
    const int np = n >> 1;           // one thread per 2 rows

    const int threads = 128;
    const int blocks = (np + threads - 1) / threads;
    lnn_tau_kernel<<<blocks, threads>>>(x, W1, b1, W2, b2, W3, b3, W4, b4, out, n);
}